// round 16
// baseline (speedup 1.0000x reference)
#include <cuda_runtime.h>

#define N_MAX 50000
#define E_MAX 800000
#define IN_FEATS 128
#define HF 64

// Scratch (device globals; no allocation allowed)
__device__ int   g_cnt[N_MAX];
__device__ int   g_off[N_MAX + 1];
__device__ int   g_cur[N_MAX];
__device__ int   g_bsum[256];
__device__ int   g_esrc[E_MAX];
__device__ float g_dinv[N_MAX];
__device__ float g_x[N_MAX * HF];
__device__ float g_f1[N_MAX * HF];
__device__ float g_f2[N_MAX * HF];
__device__ float g_M[HF * 192];

// ---------------------------------------------------------------------------
// count: 4 edges per thread (155.8us-measured config)
__global__ void count_kernel(const int* __restrict__ dst, int e) {
    int i = (blockIdx.x * blockDim.x + threadIdx.x) * 4;
    if (i + 3 < e) {
        int4 d = *reinterpret_cast<const int4*>(dst + i);
        atomicAdd(&g_cnt[d.x], 1);
        atomicAdd(&g_cnt[d.y], 1);
        atomicAdd(&g_cnt[d.z], 1);
        atomicAdd(&g_cnt[d.w], 1);
    } else {
        for (; i < e; i++) atomicAdd(&g_cnt[dst[i]], 1);
    }
}

__global__ void scan1_kernel(int n) {
    __shared__ int sh[256];
    int t = threadIdx.x;
    int i = blockIdx.x * 256 + t;
    int v = (i < n) ? g_cnt[i] : 0;
    sh[t] = v;
    __syncthreads();
#pragma unroll
    for (int o = 1; o < 256; o <<= 1) {
        int add = (t >= o) ? sh[t - o] : 0;
        __syncthreads();
        sh[t] += add;
        __syncthreads();
    }
    if (i < n) g_off[i] = sh[t] - v;
    if (t == 255) g_bsum[blockIdx.x] = sh[255];
}

__global__ void scan3_kernel(int n, int e, int nb) {
    __shared__ int sh[256];
    int t = threadIdx.x;
    sh[t] = (t < nb) ? g_bsum[t] : 0;
    __syncthreads();
#pragma unroll
    for (int o = 1; o < 256; o <<= 1) {
        int add = (t >= o) ? sh[t - o] : 0;
        __syncthreads();
        sh[t] += add;
        __syncthreads();
    }
    int boff = (blockIdx.x == 0) ? 0 : sh[blockIdx.x - 1];
    int i = blockIdx.x * 256 + t;
    if (i < n) {
        int o = g_off[i] + boff;
        g_off[i] = o;
        g_cur[i] = o;
        g_dinv[i] = rsqrtf(fmaxf((float)g_cnt[i], 1.0f));
    }
    if (i == 0) g_off[n] = e;
}

// fill: scalar (measured best)
__global__ void fill_kernel(const int* __restrict__ src,
                            const int* __restrict__ dst, int e) {
    int i = blockIdx.x * blockDim.x + threadIdx.x;
    if (i < e) {
        int d = dst[i];
        int pos = atomicAdd(&g_cur[d], 1);
        g_esrc[pos] = src[i];
    }
}

// ---------------------------------------------------------------------------
// Gather SpMM (measured-best layout: 16 lanes/edge float4, 2 edges in flight,
// next-index prefetch, shfl_xor(16) reduction). 512-thread blocks.
__global__ __launch_bounds__(512) void spmm_kernel(int n, int step) {
    const float* fin = (step == 0) ? g_x : g_f1;
    float* fout      = (step == 0) ? g_f1 : g_f2;
    int w = (blockIdx.x * blockDim.x + threadIdx.x) >> 5;
    int lane = threadIdx.x & 31;
    if (w >= n) return;
    int c = lane & 15;
    int pair = lane >> 4;
    int beg = g_off[w];
    int end = g_off[w + 1];
    const float4* F4 = reinterpret_cast<const float4*>(fin);
    float4 acc = make_float4(0.f, 0.f, 0.f, 0.f);

    int j = beg + pair;
    int s_next = (j < end) ? __ldg(&g_esrc[j]) : 0;
    while (j < end) {
        int s = s_next;
        int jn = j + 2;
        if (jn < end) s_next = __ldg(&g_esrc[jn]);
        float wt = __ldg(&g_dinv[s]);
        float4 v = __ldg(&F4[(size_t)s * 16 + c]);
        acc.x = fmaf(wt, v.x, acc.x);
        acc.y = fmaf(wt, v.y, acc.y);
        acc.z = fmaf(wt, v.z, acc.z);
        acc.w = fmaf(wt, v.w, acc.w);
        j = jn;
    }

    acc.x += __shfl_xor_sync(0xffffffffu, acc.x, 16);
    acc.y += __shfl_xor_sync(0xffffffffu, acc.y, 16);
    acc.z += __shfl_xor_sync(0xffffffffu, acc.z, 16);
    acc.w += __shfl_xor_sync(0xffffffffu, acc.w, 16);

    if (pair == 0) {
        float wd = g_dinv[w];
        float4 xv = __ldg(&F4[(size_t)w * 16 + c]);
        float4 r = make_float4(xv.x - wd * acc.x, xv.y - wd * acc.y,
                               xv.z - wd * acc.z, xv.w - wd * acc.w);
        reinterpret_cast<float4*>(fout)[(size_t)w * 16 + c] = r;
    }
}

// ---------------------------------------------------------------------------
// GEMM1 (best-measured version, unchanged)
__global__ __launch_bounds__(256) void gemm1_kernel(
    const float* __restrict__ A, const float* __restrict__ W1,
    const float* __restrict__ b1, int n) {
    __shared__ float As[32][132];
    __shared__ float Bs[32][68];
    int t = threadIdx.x;
    int m0 = blockIdx.x * 128;
    int tx = t & 7, ty = t >> 3;
    int kv = t & 7, m4 = t >> 3;

    float acc[4][8];
#pragma unroll
    for (int i = 0; i < 4; i++)
#pragma unroll
        for (int j = 0; j < 8; j++) acc[i][j] = 0.f;

    for (int k0 = 0; k0 < IN_FEATS; k0 += 32) {
#pragma unroll
        for (int i = 0; i < 4; i++) {
            int m = m4 * 4 + i;
            int gm = m0 + m;
            float4 v = make_float4(0.f, 0.f, 0.f, 0.f);
            if (gm < n)
                v = *reinterpret_cast<const float4*>(A + (size_t)gm * IN_FEATS + k0 + kv * 4);
            As[kv * 4 + 0][m] = v.x;
            As[kv * 4 + 1][m] = v.y;
            As[kv * 4 + 2][m] = v.z;
            As[kv * 4 + 3][m] = v.w;
        }
#pragma unroll
        for (int i = 0; i < 2; i++) {
            int fl = t * 2 + i;
            int nn = fl >> 3, kv2 = fl & 7;
            float4 v = *reinterpret_cast<const float4*>(W1 + (size_t)nn * IN_FEATS + k0 + kv2 * 4);
            Bs[kv2 * 4 + 0][nn] = v.x;
            Bs[kv2 * 4 + 1][nn] = v.y;
            Bs[kv2 * 4 + 2][nn] = v.z;
            Bs[kv2 * 4 + 3][nn] = v.w;
        }
        __syncthreads();
#pragma unroll
        for (int k = 0; k < 32; k++) {
            float4 a = *reinterpret_cast<float4*>(&As[k][ty * 4]);
            float4 bA = *reinterpret_cast<float4*>(&Bs[k][tx * 8]);
            float4 bB = *reinterpret_cast<float4*>(&Bs[k][tx * 8 + 4]);
            float av[4] = {a.x, a.y, a.z, a.w};
            float bv[8] = {bA.x, bA.y, bA.z, bA.w, bB.x, bB.y, bB.z, bB.w};
#pragma unroll
            for (int i = 0; i < 4; i++)
#pragma unroll
                for (int j = 0; j < 8; j++)
                    acc[i][j] = fmaf(av[i], bv[j], acc[i][j]);
        }
        __syncthreads();
    }
#pragma unroll
    for (int i = 0; i < 4; i++) {
        int gm = m0 + ty * 4 + i;
        if (gm < n) {
#pragma unroll
            for (int j = 0; j < 8; j++) {
                float v = acc[i][j] + b1[tx * 8 + j];
                g_x[(size_t)gm * HF + tx * 8 + j] = v > 0.f ? v : 0.f;
            }
        }
    }
}

// ---------------------------------------------------------------------------
__global__ void buildM_kernel(const float* __restrict__ W2) {
    int t = blockIdx.x * blockDim.x + threadIdx.x;
    if (t >= HF * 192) return;
    int r = t / 192, k = t % 192;
    int p = k >> 6, c = k & 63;
    const float cA[3] = {3.0f, -3.0f, 0.75f};
    const float cB[3] = {0.0f, 3.0f, -1.5f};
    const float cC[3] = {0.0f, 0.0f, 0.75f};
    g_M[t] = cA[p] * W2[r * 192 + c]
           + cB[p] * W2[r * 192 + 64 + c]
           + cC[p] * W2[r * 192 + 128 + c];
}

// ---------------------------------------------------------------------------
// GEMM2 rank-64 pass (unchanged)
__global__ __launch_bounds__(256) void gemm2_pass_kernel(
    const float* __restrict__ b2, float* __restrict__ out, int n, int pass) {
    __shared__ float As[32][132];
    __shared__ float Bs[32][68];
    int t = threadIdx.x;
    int m0 = blockIdx.x * 128;
    int tx = t & 7, ty = t >> 3;
    int kv = t & 7, m4 = t >> 3;
    const float* S = (pass == 0) ? g_x : (pass == 1) ? g_f1 : g_f2;

    float acc[4][8];
#pragma unroll
    for (int i = 0; i < 4; i++)
#pragma unroll
        for (int j = 0; j < 8; j++) acc[i][j] = 0.f;

#pragma unroll
    for (int cch = 0; cch < 2; cch++) {
        int koff = cch * 32;
#pragma unroll
        for (int i = 0; i < 4; i++) {
            int m = m4 * 4 + i;
            int gm = m0 + m;
            float4 v = make_float4(0.f, 0.f, 0.f, 0.f);
            if (gm < n)
                v = *reinterpret_cast<const float4*>(S + (size_t)gm * HF + koff + kv * 4);
            As[kv * 4 + 0][m] = v.x;
            As[kv * 4 + 1][m] = v.y;
            As[kv * 4 + 2][m] = v.z;
            As[kv * 4 + 3][m] = v.w;
        }
#pragma unroll
        for (int i = 0; i < 2; i++) {
            int fl = t * 2 + i;
            int nn = fl >> 3, kv2 = fl & 7;
            float4 v = *reinterpret_cast<const float4*>(
                g_M + (size_t)nn * 192 + pass * 64 + koff + kv2 * 4);
            Bs[kv2 * 4 + 0][nn] = v.x;
            Bs[kv2 * 4 + 1][nn] = v.y;
            Bs[kv2 * 4 + 2][nn] = v.z;
            Bs[kv2 * 4 + 3][nn] = v.w;
        }
        __syncthreads();
#pragma unroll
        for (int k = 0; k < 32; k++) {
            float4 a = *reinterpret_cast<float4*>(&As[k][ty * 4]);
            float4 bA = *reinterpret_cast<float4*>(&Bs[k][tx * 8]);
            float4 bB = *reinterpret_cast<float4*>(&Bs[k][tx * 8 + 4]);
            float av[4] = {a.x, a.y, a.z, a.w};
            float bv[8] = {bA.x, bA.y, bA.z, bA.w, bB.x, bB.y, bB.z, bB.w};
#pragma unroll
            for (int i = 0; i < 4; i++)
#pragma unroll
                for (int j = 0; j < 8; j++)
                    acc[i][j] = fmaf(av[i], bv[j], acc[i][j]);
        }
        __syncthreads();
    }
#pragma unroll
    for (int i = 0; i < 4; i++) {
        int gm = m0 + ty * 4 + i;
        if (gm < n) {
            float4* dst = reinterpret_cast<float4*>(&out[(size_t)gm * HF + tx * 8]);
            if (pass == 0) {
                float o[8];
#pragma unroll
                for (int j = 0; j < 8; j++) o[j] = acc[i][j] + b2[tx * 8 + j];
                dst[0] = make_float4(o[0], o[1], o[2], o[3]);
                dst[1] = make_float4(o[4], o[5], o[6], o[7]);
            } else {
                float4 p0 = dst[0], p1 = dst[1];
                dst[0] = make_float4(p0.x + acc[i][0], p0.y + acc[i][1],
                                     p0.z + acc[i][2], p0.w + acc[i][3]);
                dst[1] = make_float4(p1.x + acc[i][4], p1.y + acc[i][5],
                                     p1.z + acc[i][6], p1.w + acc[i][7]);
            }
        }
    }
}

// ---------------------------------------------------------------------------
extern "C" void kernel_launch(void* const* d_in, const int* in_sizes, int n_in,
                              void* d_out, int out_size) {
    const float* features = (const float*)d_in[0];
    const int*   src      = (const int*)d_in[1];
    const int*   dst      = (const int*)d_in[2];
    const float* W1       = (const float*)d_in[3];
    const float* b1       = (const float*)d_in[4];
    const float* W2       = (const float*)d_in[5];
    const float* b2       = (const float*)d_in[6];
    float* out = (float*)d_out;

    int n = in_sizes[0] / IN_FEATS;   // 50000
    int e = in_sizes[1];              // 800000
    int nb = (n + 255) / 256;         // 196
    int gb = (n + 127) / 128;         // GEMM grid
    int eb4 = (e / 4 + 255) / 256;    // vectorized count

    cudaStream_t sA;
    cudaStreamCreateWithFlags(&sA, cudaStreamNonBlocking);
    cudaEvent_t e0, eA, eG, eS0, eB;
    cudaEventCreateWithFlags(&e0,  cudaEventDisableTiming);
    cudaEventCreateWithFlags(&eA,  cudaEventDisableTiming);
    cudaEventCreateWithFlags(&eG,  cudaEventDisableTiming);
    cudaEventCreateWithFlags(&eS0, cudaEventDisableTiming);
    cudaEventCreateWithFlags(&eB,  cudaEventDisableTiming);

    cudaEventRecord(e0, 0);
    cudaStreamWaitEvent(sA, e0, 0);

    // Kernel submission order chosen so spmm_kernel(step=0) is the 6th kernel
    // (ncu -s 5 -c 1 captures it): gemm1, count, scan1, scan3, fill, spmm0.

    // #0: main stream — gemm1
    gemm1_kernel<<<gb, 256>>>(features, W1, b1, n);
    cudaEventRecord(eG, 0);   // g_x ready

    // #1-#4: side stream — CSR build chain
    void* cnt_ptr = nullptr;
    cudaGetSymbolAddress(&cnt_ptr, g_cnt);
    cudaMemsetAsync(cnt_ptr, 0, (size_t)n * sizeof(int), sA);
    count_kernel<<<eb4, 256, 0, sA>>>(dst, e);
    scan1_kernel<<<nb, 256, 0, sA>>>(n);
    scan3_kernel<<<nb, 256, 0, sA>>>(n, e, nb);
    fill_kernel<<<(e + 255) / 256, 256, 0, sA>>>(src, dst, e);
    cudaEventRecord(eA, sA);

    // #5: main stream — spmm0 (needs g_x via stream order, CSR via eA)
    cudaStreamWaitEvent(0, eA, 0);
    int spmm_blocks = (n * 32 + 511) / 512;   // 512-thread blocks, warp/node
    spmm_kernel<<<spmm_blocks, 512>>>(n, 0);  // f1 = L x
    cudaEventRecord(eS0, 0);

    // #6: side stream — buildM (after fill in stream order; precedes pass0)
    buildM_kernel<<<(HF * 192 + 255) / 256, 256, 0, sA>>>(W2);
    // #7: side — pass0 (needs g_M: stream order; g_x: eG), hides under spmm0
    cudaStreamWaitEvent(sA, eG, 0);
    gemm2_pass_kernel<<<gb, 256, 0, sA>>>(b2, out, n, 0);
    // #8: side — pass1 (needs f1: eS0), hides under spmm1
    cudaStreamWaitEvent(sA, eS0, 0);
    gemm2_pass_kernel<<<gb, 256, 0, sA>>>(b2, out, n, 1);
    cudaEventRecord(eB, sA);

    // #9: main — spmm1 (f2 = L f1)
    spmm_kernel<<<spmm_blocks, 512>>>(n, 1);

    // #10: main — pass2 tail (needs f2: stream order; out from pass1: eB)
    cudaStreamWaitEvent(0, eB, 0);
    gemm2_pass_kernel<<<gb, 256>>>(b2, out, n, 2);

    cudaEventDestroy(e0);
    cudaEventDestroy(eA);
    cudaEventDestroy(eG);
    cudaEventDestroy(eS0);
    cudaEventDestroy(eB);
    cudaStreamDestroy(sA);
}

// round 17
// speedup vs baseline: 1.0416x; 1.0416x over previous
#include <cuda_runtime.h>

#define N_MAX 50000
#define E_MAX 800000
#define IN_FEATS 128
#define HF 64

// Scratch (device globals; no allocation allowed).
// g_cnt relies on zero-init at module load; fill_kernel re-zeroes it at the
// end of every call, so each kernel_launch invocation sees g_cnt == 0.
__device__ int   g_cnt[N_MAX];
__device__ int   g_off[N_MAX + 1];
__device__ int   g_cur[N_MAX];
__device__ int   g_esrc[E_MAX];
__device__ float g_dinv[N_MAX];
__device__ float g_x[N_MAX * HF];
__device__ float g_f1[N_MAX * HF];
__device__ float g_f2[N_MAX * HF];
__device__ float g_M[HF * 192];

// ---------------------------------------------------------------------------
// count: 4 edges per thread (measured-best config)
__global__ void count_kernel(const int* __restrict__ dst, int e) {
    int i = (blockIdx.x * blockDim.x + threadIdx.x) * 4;
    if (i + 3 < e) {
        int4 d = *reinterpret_cast<const int4*>(dst + i);
        atomicAdd(&g_cnt[d.x], 1);
        atomicAdd(&g_cnt[d.y], 1);
        atomicAdd(&g_cnt[d.z], 1);
        atomicAdd(&g_cnt[d.w], 1);
    } else {
        for (; i < e; i++) atomicAdd(&g_cnt[dst[i]], 1);
    }
}

// ---------------------------------------------------------------------------
// Fused scan (replaces scan1 + scan3): each block does its local exclusive
// scan AND directly sums all preceding g_cnt values for its block offset.
__global__ void scan_kernel(int n, int e) {
    __shared__ int sh[256];
    __shared__ int red[256];
    int t = threadIdx.x;
    int b = blockIdx.x;
    int i = b * 256 + t;
    int v = (i < n) ? g_cnt[i] : 0;

    // local exclusive scan of this block's 256 counts
    sh[t] = v;
    __syncthreads();
#pragma unroll
    for (int o = 1; o < 256; o <<= 1) {
        int add = (t >= o) ? sh[t - o] : 0;
        __syncthreads();
        sh[t] += add;
        __syncthreads();
    }
    int local_excl = sh[t] - v;

    // block offset = sum of g_cnt[0 .. b*256)  (brute force, L2-resident)
    int s = 0;
    int lim = b * 256;
    for (int idx = t; idx < lim; idx += 256) s += g_cnt[idx];
    red[t] = s;
    __syncthreads();
#pragma unroll
    for (int o = 128; o > 0; o >>= 1) {
        if (t < o) red[t] += red[t + o];
        __syncthreads();
    }
    int boff = red[0];

    if (i < n) {
        int o = local_excl + boff;
        g_off[i] = o;
        g_cur[i] = o;
        g_dinv[i] = rsqrtf(fmaxf((float)v, 1.0f));
    }
    if (i == 0) g_off[n] = e;
}

// fill: scalar (measured best) + re-zero g_cnt for the next invocation
// (g_cnt is dead after scan_kernel; fill runs after it in stream order).
__global__ void fill_kernel(const int* __restrict__ src,
                            const int* __restrict__ dst, int e, int n) {
    int i = blockIdx.x * blockDim.x + threadIdx.x;
    if (i < e) {
        int d = dst[i];
        int pos = atomicAdd(&g_cur[d], 1);
        g_esrc[pos] = src[i];
    }
    if (i < n) g_cnt[i] = 0;
}

// ---------------------------------------------------------------------------
// Gather SpMM (measured-best: 16 lanes/edge float4, 2 edges in flight,
// next-index prefetch, shfl_xor(16) reduction, 256-thread blocks).
__global__ __launch_bounds__(256) void spmm_kernel(int n, int step) {
    const float* fin = (step == 0) ? g_x : g_f1;
    float* fout      = (step == 0) ? g_f1 : g_f2;
    int w = (blockIdx.x * blockDim.x + threadIdx.x) >> 5;
    int lane = threadIdx.x & 31;
    if (w >= n) return;
    int c = lane & 15;
    int pair = lane >> 4;
    int beg = g_off[w];
    int end = g_off[w + 1];
    const float4* F4 = reinterpret_cast<const float4*>(fin);
    float4 acc = make_float4(0.f, 0.f, 0.f, 0.f);

    int j = beg + pair;
    int s_next = (j < end) ? __ldg(&g_esrc[j]) : 0;
    while (j < end) {
        int s = s_next;
        int jn = j + 2;
        if (jn < end) s_next = __ldg(&g_esrc[jn]);
        float wt = __ldg(&g_dinv[s]);
        float4 v = __ldg(&F4[(size_t)s * 16 + c]);
        acc.x = fmaf(wt, v.x, acc.x);
        acc.y = fmaf(wt, v.y, acc.y);
        acc.z = fmaf(wt, v.z, acc.z);
        acc.w = fmaf(wt, v.w, acc.w);
        j = jn;
    }

    acc.x += __shfl_xor_sync(0xffffffffu, acc.x, 16);
    acc.y += __shfl_xor_sync(0xffffffffu, acc.y, 16);
    acc.z += __shfl_xor_sync(0xffffffffu, acc.z, 16);
    acc.w += __shfl_xor_sync(0xffffffffu, acc.w, 16);

    if (pair == 0) {
        float wd = g_dinv[w];
        float4 xv = __ldg(&F4[(size_t)w * 16 + c]);
        float4 r = make_float4(xv.x - wd * acc.x, xv.y - wd * acc.y,
                               xv.z - wd * acc.z, xv.w - wd * acc.w);
        reinterpret_cast<float4*>(fout)[(size_t)w * 16 + c] = r;
    }
}

// ---------------------------------------------------------------------------
// GEMM1 (best-measured version, unchanged)
__global__ __launch_bounds__(256) void gemm1_kernel(
    const float* __restrict__ A, const float* __restrict__ W1,
    const float* __restrict__ b1, int n) {
    __shared__ float As[32][132];
    __shared__ float Bs[32][68];
    int t = threadIdx.x;
    int m0 = blockIdx.x * 128;
    int tx = t & 7, ty = t >> 3;
    int kv = t & 7, m4 = t >> 3;

    float acc[4][8];
#pragma unroll
    for (int i = 0; i < 4; i++)
#pragma unroll
        for (int j = 0; j < 8; j++) acc[i][j] = 0.f;

    for (int k0 = 0; k0 < IN_FEATS; k0 += 32) {
#pragma unroll
        for (int i = 0; i < 4; i++) {
            int m = m4 * 4 + i;
            int gm = m0 + m;
            float4 v = make_float4(0.f, 0.f, 0.f, 0.f);
            if (gm < n)
                v = *reinterpret_cast<const float4*>(A + (size_t)gm * IN_FEATS + k0 + kv * 4);
            As[kv * 4 + 0][m] = v.x;
            As[kv * 4 + 1][m] = v.y;
            As[kv * 4 + 2][m] = v.z;
            As[kv * 4 + 3][m] = v.w;
        }
#pragma unroll
        for (int i = 0; i < 2; i++) {
            int fl = t * 2 + i;
            int nn = fl >> 3, kv2 = fl & 7;
            float4 v = *reinterpret_cast<const float4*>(W1 + (size_t)nn * IN_FEATS + k0 + kv2 * 4);
            Bs[kv2 * 4 + 0][nn] = v.x;
            Bs[kv2 * 4 + 1][nn] = v.y;
            Bs[kv2 * 4 + 2][nn] = v.z;
            Bs[kv2 * 4 + 3][nn] = v.w;
        }
        __syncthreads();
#pragma unroll
        for (int k = 0; k < 32; k++) {
            float4 a = *reinterpret_cast<float4*>(&As[k][ty * 4]);
            float4 bA = *reinterpret_cast<float4*>(&Bs[k][tx * 8]);
            float4 bB = *reinterpret_cast<float4*>(&Bs[k][tx * 8 + 4]);
            float av[4] = {a.x, a.y, a.z, a.w};
            float bv[8] = {bA.x, bA.y, bA.z, bA.w, bB.x, bB.y, bB.z, bB.w};
#pragma unroll
            for (int i = 0; i < 4; i++)
#pragma unroll
                for (int j = 0; j < 8; j++)
                    acc[i][j] = fmaf(av[i], bv[j], acc[i][j]);
        }
        __syncthreads();
    }
#pragma unroll
    for (int i = 0; i < 4; i++) {
        int gm = m0 + ty * 4 + i;
        if (gm < n) {
#pragma unroll
            for (int j = 0; j < 8; j++) {
                float v = acc[i][j] + b1[tx * 8 + j];
                g_x[(size_t)gm * HF + tx * 8 + j] = v > 0.f ? v : 0.f;
            }
        }
    }
}

// ---------------------------------------------------------------------------
__global__ void buildM_kernel(const float* __restrict__ W2) {
    int t = blockIdx.x * blockDim.x + threadIdx.x;
    if (t >= HF * 192) return;
    int r = t / 192, k = t % 192;
    int p = k >> 6, c = k & 63;
    const float cA[3] = {3.0f, -3.0f, 0.75f};
    const float cB[3] = {0.0f, 3.0f, -1.5f};
    const float cC[3] = {0.0f, 0.0f, 0.75f};
    g_M[t] = cA[p] * W2[r * 192 + c]
           + cB[p] * W2[r * 192 + 64 + c]
           + cC[p] * W2[r * 192 + 128 + c];
}

// ---------------------------------------------------------------------------
// GEMM2 rank-64 pass (unchanged)
__global__ __launch_bounds__(256) void gemm2_pass_kernel(
    const float* __restrict__ b2, float* __restrict__ out, int n, int pass) {
    __shared__ float As[32][132];
    __shared__ float Bs[32][68];
    int t = threadIdx.x;
    int m0 = blockIdx.x * 128;
    int tx = t & 7, ty = t >> 3;
    int kv = t & 7, m4 = t >> 3;
    const float* S = (pass == 0) ? g_x : (pass == 1) ? g_f1 : g_f2;

    float acc[4][8];
#pragma unroll
    for (int i = 0; i < 4; i++)
#pragma unroll
        for (int j = 0; j < 8; j++) acc[i][j] = 0.f;

#pragma unroll
    for (int cch = 0; cch < 2; cch++) {
        int koff = cch * 32;
#pragma unroll
        for (int i = 0; i < 4; i++) {
            int m = m4 * 4 + i;
            int gm = m0 + m;
            float4 v = make_float4(0.f, 0.f, 0.f, 0.f);
            if (gm < n)
                v = *reinterpret_cast<const float4*>(S + (size_t)gm * HF + koff + kv * 4);
            As[kv * 4 + 0][m] = v.x;
            As[kv * 4 + 1][m] = v.y;
            As[kv * 4 + 2][m] = v.z;
            As[kv * 4 + 3][m] = v.w;
        }
#pragma unroll
        for (int i = 0; i < 2; i++) {
            int fl = t * 2 + i;
            int nn = fl >> 3, kv2 = fl & 7;
            float4 v = *reinterpret_cast<const float4*>(
                g_M + (size_t)nn * 192 + pass * 64 + koff + kv2 * 4);
            Bs[kv2 * 4 + 0][nn] = v.x;
            Bs[kv2 * 4 + 1][nn] = v.y;
            Bs[kv2 * 4 + 2][nn] = v.z;
            Bs[kv2 * 4 + 3][nn] = v.w;
        }
        __syncthreads();
#pragma unroll
        for (int k = 0; k < 32; k++) {
            float4 a = *reinterpret_cast<float4*>(&As[k][ty * 4]);
            float4 bA = *reinterpret_cast<float4*>(&Bs[k][tx * 8]);
            float4 bB = *reinterpret_cast<float4*>(&Bs[k][tx * 8 + 4]);
            float av[4] = {a.x, a.y, a.z, a.w};
            float bv[8] = {bA.x, bA.y, bA.z, bA.w, bB.x, bB.y, bB.z, bB.w};
#pragma unroll
            for (int i = 0; i < 4; i++)
#pragma unroll
                for (int j = 0; j < 8; j++)
                    acc[i][j] = fmaf(av[i], bv[j], acc[i][j]);
        }
        __syncthreads();
    }
#pragma unroll
    for (int i = 0; i < 4; i++) {
        int gm = m0 + ty * 4 + i;
        if (gm < n) {
            float4* dst = reinterpret_cast<float4*>(&out[(size_t)gm * HF + tx * 8]);
            if (pass == 0) {
                float o[8];
#pragma unroll
                for (int j = 0; j < 8; j++) o[j] = acc[i][j] + b2[tx * 8 + j];
                dst[0] = make_float4(o[0], o[1], o[2], o[3]);
                dst[1] = make_float4(o[4], o[5], o[6], o[7]);
            } else {
                float4 p0 = dst[0], p1 = dst[1];
                dst[0] = make_float4(p0.x + acc[i][0], p0.y + acc[i][1],
                                     p0.z + acc[i][2], p0.w + acc[i][3]);
                dst[1] = make_float4(p1.x + acc[i][4], p1.y + acc[i][5],
                                     p1.z + acc[i][6], p1.w + acc[i][7]);
            }
        }
    }
}

// ---------------------------------------------------------------------------
extern "C" void kernel_launch(void* const* d_in, const int* in_sizes, int n_in,
                              void* d_out, int out_size) {
    const float* features = (const float*)d_in[0];
    const int*   src      = (const int*)d_in[1];
    const int*   dst      = (const int*)d_in[2];
    const float* W1       = (const float*)d_in[3];
    const float* b1       = (const float*)d_in[4];
    const float* W2       = (const float*)d_in[5];
    const float* b2       = (const float*)d_in[6];
    float* out = (float*)d_out;

    int n = in_sizes[0] / IN_FEATS;   // 50000
    int e = in_sizes[1];              // 800000
    int nb = (n + 255) / 256;         // 196
    int gb = (n + 127) / 128;         // GEMM grid
    int eb4 = (e / 4 + 255) / 256;    // vectorized count

    cudaStream_t sA;
    cudaStreamCreateWithFlags(&sA, cudaStreamNonBlocking);
    cudaEvent_t e0, eA, eG, eS0, eB;
    cudaEventCreateWithFlags(&e0,  cudaEventDisableTiming);
    cudaEventCreateWithFlags(&eA,  cudaEventDisableTiming);
    cudaEventCreateWithFlags(&eG,  cudaEventDisableTiming);
    cudaEventCreateWithFlags(&eS0, cudaEventDisableTiming);
    cudaEventCreateWithFlags(&eB,  cudaEventDisableTiming);

    cudaEventRecord(e0, 0);
    cudaStreamWaitEvent(sA, e0, 0);

    // --- side stream: CSR build chain (3 nodes: count, scan, fill) ---
    // (no memset: g_cnt zeroed by the previous call's fill / module init)
    count_kernel<<<eb4, 256, 0, sA>>>(dst, e);
    scan_kernel<<<nb, 256, 0, sA>>>(n, e);
    fill_kernel<<<(e + 255) / 256, 256, 0, sA>>>(src, dst, e, n);
    cudaEventRecord(eA, sA);

    // --- main stream: dense prologue ---
    gemm1_kernel<<<gb, 256>>>(features, W1, b1, n);
    buildM_kernel<<<(HF * 192 + 255) / 256, 256>>>(W2);
    cudaEventRecord(eG, 0);   // g_x and g_M ready

    // join: spmm0 needs g_x and CSR
    cudaStreamWaitEvent(0, eA, 0);
    int spmm_blocks = (n + 7) / 8;    // 8 warps/block, warp per node
    spmm_kernel<<<spmm_blocks, 256>>>(n, 0);         // f1 = L x
    cudaEventRecord(eS0, 0);

    // side stream: pass0 concurrent with spmm0, pass1 concurrent with spmm1
    cudaStreamWaitEvent(sA, eG, 0);
    gemm2_pass_kernel<<<gb, 256, 0, sA>>>(b2, out, n, 0);
    cudaStreamWaitEvent(sA, eS0, 0);
    gemm2_pass_kernel<<<gb, 256, 0, sA>>>(b2, out, n, 1);
    cudaEventRecord(eB, sA);

    // main stream: spmm1 (f2 = L f1)
    spmm_kernel<<<spmm_blocks, 256>>>(n, 1);

    // tail: pass2 needs f2 (main) and out from pass1 (side)
    cudaStreamWaitEvent(0, eB, 0);
    gemm2_pass_kernel<<<gb, 256>>>(b2, out, n, 2);

    cudaEventDestroy(e0);
    cudaEventDestroy(eA);
    cudaEventDestroy(eG);
    cudaEventDestroy(eS0);
    cudaEventDestroy(eB);
    cudaStreamDestroy(sA);
}